// round 17
// baseline (speedup 1.0000x reference)
#include <cuda_runtime.h>
#include <cuda_fp16.h>
#include <math.h>
#include <stddef.h>
#include <stdint.h>

// ---------------------------------------------------------------------------
// Problem constants
// ---------------------------------------------------------------------------
#define B_TOK   16384
#define D_IN    512
#define D_OUT   64
#define H1      64
#define H2      32
#define GH      32
#define NEXP    6
#define NCAT    480
#define NCATP   512
#define LN_EPS  1e-5f

// ---------------------------------------------------------------------------
// Device scratch
// ---------------------------------------------------------------------------
__device__ __align__(16) __half g_wh[NCATP * D_IN];            // [n][k] fp16
__device__ float g_bc[NCATP];
__device__ __align__(16) __half g_Hh[(size_t)B_TOK * NCATP];   // H fp16 [token][col]

__device__ __forceinline__ uint32_t smem_u32(const void* p) {
    uint32_t a;
    asm("{ .reg .u64 t; cvta.to.shared.u64 t, %1; cvt.u32.u64 %0, t; }" : "=r"(a) : "l"(p));
    return a;
}

// ---------------------------------------------------------------------------
// Kernel: prep = pack W to fp16 [n][k] + bias (W only; conv folded into gemm)
// ---------------------------------------------------------------------------
__global__ __launch_bounds__(256) void prep_kernel(
    const float* __restrict__ sw1, const float* __restrict__ sb1,
    const float* __restrict__ gw1, const float* __restrict__ gb1,
    const float* __restrict__ sgw1, const float* __restrict__ sgb1,
    const float* __restrict__ ggw1, const float* __restrict__ ggb1) {
    int base = blockIdx.x * 1024 + threadIdx.x;
#pragma unroll
    for (int u = 0; u < 4; u++) {
        int idx = base + u * 256;                            // over 512*512
        int n = idx >> 9, k = idx & 511;
        float w = 0.f;
        if (n < 384) {
            int e = n >> 6, j = n & 63;
            w = (e < 2) ? sw1[((size_t)e * D_IN + k) * 64 + j]
                        : gw1[((size_t)(e - 2) * D_IN + k) * 64 + j];
        } else if (n < 480) {
            int m = n - 384, s = m >> 5, j = m & 31;
            w = (s == 0) ? sgw1[k * 32 + j]
                         : ggw1[((size_t)(s - 1) * D_IN + k) * 32 + j];
        }
        g_wh[idx] = __float2half_rn(w);
        if (idx < NCATP) {
            float b = 0.f;
            if (idx < 384) {
                int e = idx >> 6, j = idx & 63;
                b = (e < 2) ? sb1[e * 64 + j] : gb1[(e - 2) * 64 + j];
            } else if (idx < 480) {
                int m = idx - 384, s = m >> 5, j = m & 31;
                b = (s == 0) ? sgb1[j] : ggb1[(s - 1) * GH + j];
            }
            g_bc[idx] = b;
        }
    }
}

// ---------------------------------------------------------------------------
// Kernel: H = silu(v @ W + b) fp16 token-major. A loaded as FP32 from v,
// converted to fp16 in smem one chunk ahead of compute (single barrier/chunk).
// 4-stage cp.async ring (distance 2), K chunks of 32. CTA 128x128.
// A32 rows 128B, swizzle seg^(row&7); A16/B16 rows 64B, swizzle seg^((row>>1)&3).
// ---------------------------------------------------------------------------
#define KCH     32
#define A32B    (128 * 128)                 // 16384 per stage
#define B16B    (128 * 64)                  // 8192 per stage
#define NSTG    4
#define SMO_A32 0                           // 4 x 16384 = 65536
#define SMO_B16 65536                       // 4 x 8192  = 32768
#define SMO_A16 98304                       // 2 x 8192  = 16384
#define SMO_BIAS 114688
#define GEMM_SMEM (SMO_BIAS + 512)          // 115200
#define NCHUNK  (D_IN / KCH)                // 16

#define CPASYNC16(dst, src) \
    asm volatile("cp.async.cg.shared.global [%0], [%1], 16;" :: "r"(dst), "l"(src))

__device__ __forceinline__ void ldsm_x4(uint32_t* r, uint32_t a) {
    asm volatile("ldmatrix.sync.aligned.m8n8.x4.shared.b16 {%0,%1,%2,%3}, [%4];"
                 : "=r"(r[0]), "=r"(r[1]), "=r"(r[2]), "=r"(r[3]) : "r"(a));
}
__device__ __forceinline__ void ldsm_x2t(uint32_t* r, uint32_t a) {
    asm volatile("ldmatrix.sync.aligned.m8n8.x2.trans.shared.b16 {%0,%1}, [%2];"
                 : "=r"(r[0]), "=r"(r[1]) : "r"(a));
}
__device__ __forceinline__ void mma_f16(float* c, const uint32_t* a, uint32_t b0, uint32_t b1) {
    asm volatile(
        "mma.sync.aligned.m16n8k16.row.col.f32.f16.f16.f32 "
        "{%0,%1,%2,%3}, {%4,%5,%6,%7}, {%8,%9}, {%0,%1,%2,%3};"
        : "+f"(c[0]), "+f"(c[1]), "+f"(c[2]), "+f"(c[3])
        : "r"(a[0]), "r"(a[1]), "r"(a[2]), "r"(a[3]), "r"(b0), "r"(b1));
}
__device__ __forceinline__ float silu_f(float x) { return x / (1.f + __expf(-x)); }

__global__ void __launch_bounds__(256, 2) gemm1_mma_kernel(const float* __restrict__ v) {
    extern __shared__ char smem[];
    const uint32_t sb = smem_u32(smem);
    const int tid  = threadIdx.x;
    const int lane = tid & 31;
    const int warp = tid >> 5;
    const int wm = warp >> 2;
    const int wn = warp & 3;
    const int bm = blockIdx.y * 128;
    const int bn = blockIdx.x * 128;

    if (tid < 128) ((float*)(smem + SMO_BIAS))[tid] = g_bc[bn + tid];

    // ---- load geometry ----
    // A32 (fp32): 128 rows x 8 segs(16B); 4 segs/thread: row=tid>>1, segs (tid&1)*4+j
    const int ar  = tid >> 1;
    const int ah_ = tid & 1;
    // B16 (fp16): 128 rows x 4 segs(16B); 2 segs/thread: row=tid>>1, segs (tid&1)*2+j
    const int brsw_ld = (ar >> 1) & 3;

    // ---- ldmatrix lane geometry (fp16, 64B rows, swizzle (row>>1)&3) ----
    const int mi = lane >> 3;
    const int a_row = (lane & 7) + ((mi & 1) << 3);
    const int akb4  = (mi >= 2) ? 1 : 0;
    const int b_row = (lane & 7) + ((mi >= 2) ? 8 : 0);
    const int bkb4  = (mi & 1) ? 1 : 0;
    const int arsw  = (a_row >> 1) & 3;
    const int brsw  = (b_row >> 1) & 3;

    float acc[4][4][4];
#pragma unroll
    for (int i = 0; i < 4; i++)
#pragma unroll
        for (int j = 0; j < 4; j++)
#pragma unroll
            for (int u = 0; u < 4; u++) acc[i][j][u] = 0.f;

    auto load_chunk = [&](int ch, int stg) {
        const int k0 = ch * KCH;
        // A fp32
        {
            const uint32_t base = sb + SMO_A32 + stg * A32B + (uint32_t)(ar * 128);
            const float* src = v + (size_t)(bm + ar) * D_IN + k0;
#pragma unroll
            for (int j = 0; j < 4; j++) {
                int s = ah_ * 4 + j;
                CPASYNC16(base + (uint32_t)((s ^ (ar & 7)) << 4), src + s * 4);
            }
        }
        // B fp16
        {
            const uint32_t base = sb + SMO_B16 + stg * B16B + (uint32_t)(ar * 64);
            const __half* src = g_wh + (size_t)(bn + ar) * D_IN + k0;
#pragma unroll
            for (int j = 0; j < 2; j++) {
                int s = ah_ * 2 + j;
                CPASYNC16(base + (uint32_t)((s ^ brsw_ld) << 4), src + s * 8);
            }
        }
    };

    // convert chunk in A32[stg] -> A16[slot]; thread handles row=tid>>1, half=tid&1
    auto convert_chunk = [&](int stg, int slot) {
        const char* src = smem + SMO_A32 + stg * A32B + ar * 128;
        char* dst = smem + SMO_A16 + slot * 8192 + ar * 64;
#pragma unroll
        for (int j2 = 0; j2 < 2; j2++) {
            // two fp32 segs -> one fp16 seg
            int s0 = ah_ * 4 + j2 * 2;
            float4 x0 = *(const float4*)(src + ((s0 ^ (ar & 7)) << 4));
            float4 x1 = *(const float4*)(src + (((s0 + 1) ^ (ar & 7)) << 4));
            uint4 o;
            ((__half2*)&o)[0] = __floats2half2_rn(x0.x, x0.y);
            ((__half2*)&o)[1] = __floats2half2_rn(x0.z, x0.w);
            ((__half2*)&o)[2] = __floats2half2_rn(x1.x, x1.y);
            ((__half2*)&o)[3] = __floats2half2_rn(x1.z, x1.w);
            int od = ah_ * 2 + j2;
            *(uint4*)(dst + ((od ^ brsw_ld) << 4)) = o;
        }
    };

    auto compute_chunk = [&](int ch) {
        const uint32_t aBase = sb + SMO_A16 + (ch & 1) * 8192
                             + (uint32_t)((wm * 64 + a_row) * 64);
        const uint32_t bBase = sb + SMO_B16 + (ch % NSTG) * B16B
                             + (uint32_t)((wn * 32 + b_row) * 64);
#pragma unroll
        for (int kt = 0; kt < 2; kt++) {
            const uint32_t aoff = (uint32_t)(((kt * 2 + akb4) ^ arsw) << 4);
            const uint32_t boff = (uint32_t)(((kt * 2 + bkb4) ^ brsw) << 4);
            uint32_t ahr[4][4], bhr[2][4];
#pragma unroll
            for (int mt = 0; mt < 4; mt++)
                ldsm_x4(ahr[mt], aBase + mt * 1024 + aoff);
#pragma unroll
            for (int h = 0; h < 2; h++)
                ldsm_x4(bhr[h], bBase + h * 1024 + boff);
#pragma unroll
            for (int mt = 0; mt < 4; mt++)
#pragma unroll
                for (int nt = 0; nt < 4; nt++)
                    mma_f16(acc[mt][nt], ahr[mt],
                            bhr[nt >> 1][(nt & 1) * 2], bhr[nt >> 1][(nt & 1) * 2 + 1]);
        }
    };

    // prologue: prefetch chunks 0 and 1
    load_chunk(0, 0);
    asm volatile("cp.async.commit_group;");
    load_chunk(1, 1);
    asm volatile("cp.async.commit_group;");

    for (int i = 0; i < NCHUNK; i++) {
        if (i < NCHUNK - 1) {
            asm volatile("cp.async.wait_group 1;");   // chunk i arrived
        } else {
            asm volatile("cp.async.wait_group 0;");
        }
        __syncthreads();   // single barrier: orders convert(i-1)->compute(i-1),
                           // and ring-slot reuse for load(i+2)/convert(i)

        if (i + 2 < NCHUNK) {
            load_chunk(i + 2, (i + 2) % NSTG);
            asm volatile("cp.async.commit_group;");
        }
        convert_chunk(i % NSTG, i & 1);
        if (i >= 1) compute_chunk(i - 1);
    }
    __syncthreads();       // order convert(15) before compute(15)
    compute_chunk(NCHUNK - 1);
    __syncthreads();

    // Epilogue: bias + silu -> half stage [row][136] -> coalesced g_Hh rows
    {
        __half* stg = (__half*)smem;
        const float* bias = (const float*)(smem + SMO_BIAS);
#pragma unroll
        for (int mt = 0; mt < 4; mt++) {
#pragma unroll
            for (int nt = 0; nt < 4; nt++) {
                int r = wm * 64 + mt * 16 + (lane >> 2);
                int c0 = wn * 32 + nt * 8 + 2 * (lane & 3);
                float b0 = bias[c0], b1 = bias[c0 + 1];
                float y0 = silu_f(acc[mt][nt][0] + b0);
                float y1 = silu_f(acc[mt][nt][1] + b1);
                float y2 = silu_f(acc[mt][nt][2] + b0);
                float y3 = silu_f(acc[mt][nt][3] + b1);
                *(__half2*)(stg + r * 136 + c0)       = __floats2half2_rn(y0, y1);
                *(__half2*)(stg + (r + 8) * 136 + c0) = __floats2half2_rn(y2, y3);
            }
        }
        __syncthreads();
#pragma unroll
        for (int k = 0; k < 8; k++) {
            int lin = tid + k * 256;    // 0..2047
            int row = lin >> 4, s = lin & 15;
            uint4 val = *(uint4*)((char*)smem + row * 272 + s * 16);
            *(uint4*)(g_Hh + (size_t)(bm + row) * NCATP + bn + s * 8) = val;
        }
    }
}

// ---------------------------------------------------------------------------
// Kernel: tail7 — tensor-core tail. grid (B/128, 3), 256 threads (8 warps).
// (verbatim from R15/R16 — validated)
// ---------------------------------------------------------------------------
#define A7      0
#define H27     32768
#define W27     53248
#define W37     63488
#define ZAC7    72704
#define WG7     107520
#define PB2     108544
#define PB3     108800
#define PGM     109312
#define PBT     109824
#define PGW     110336
#define PGB     110592
#define T7_SMEM 110600

__global__ void __launch_bounds__(256, 2) tail7_kernel(
    const float* __restrict__ sw2, const float* __restrict__ sb2,
    const float* __restrict__ sw3, const float* __restrict__ sb3,
    const float* __restrict__ sgam, const float* __restrict__ sbet,
    const float* __restrict__ sgw2, const float* __restrict__ sgb2,
    const float* __restrict__ gw2, const float* __restrict__ gb2,
    const float* __restrict__ gw3, const float* __restrict__ gb3,
    const float* __restrict__ ggam, const float* __restrict__ gbet,
    const float* __restrict__ ggw2, const float* __restrict__ ggb2,
    float* __restrict__ out) {
    extern __shared__ char smem[];
    const uint32_t sb = smem_u32(smem);
    const int tid  = threadIdx.x;
    const int lane = tid & 31;
    const int warp = tid >> 5;
    const int ws = warp >> 2;
    const int wr = warp & 3;
    const int p  = blockIdx.y;
    const int t0 = blockIdx.x * 128;
    const int e_base = (p == 2) ? 0 : ((p == 0) ? 2 : 4);
    const int gslot  = (p == 2) ? 0 : (p + 1);

    {
        const __half* src = g_Hh + (size_t)t0 * NCATP + e_base * 64;
#pragma unroll
        for (int k = 0; k < 8; k++) {
            int lin = tid + k * 256;
            int row = lin >> 4, s = lin & 15;
            uint4 val = *(const uint4*)(src + (size_t)row * NCATP + s * 8);
            *(uint4*)(smem + A7 + row * 256 + ((s ^ (row & 7)) << 4)) = val;
        }
    }
#pragma unroll
    for (int s = 0; s < 2; s++) {
        const int e = e_base + s;
        const float* w2src = (e < 2) ? (sw2 + (size_t)e * 2048) : (gw2 + (size_t)(e - 2) * 2048);
        const float* w3src = (e < 2) ? (sw3 + (size_t)e * 2048) : (gw3 + (size_t)(e - 2) * 2048);
        __half* w2d = (__half*)(smem + W27 + s * 5120);
        __half* w3d = (__half*)(smem + W37 + s * 4608);
        for (int i = tid; i < 2048; i += 256) {
            w2d[(i >> 5) * 40 + (i & 31)] = __float2half_rn(w2src[i]);
            w3d[(i >> 6) * 72 + (i & 63)] = __float2half_rn(w3src[i]);
        }
        if (tid < H2) ((float*)(smem + PB2))[s * 32 + tid] =
            (e < 2) ? sb2[e * 32 + tid] : gb2[(e - 2) * 32 + tid];
        if (tid < D_OUT) {
            ((float*)(smem + PB3))[s * 64 + tid] = (e < 2) ? sb3[e * 64 + tid]  : gb3[(e - 2) * 64 + tid];
            ((float*)(smem + PGM))[s * 64 + tid] = (e < 2) ? sgam[e * 64 + tid] : ggam[(e - 2) * 64 + tid];
            ((float*)(smem + PBT))[s * 64 + tid] = (e < 2) ? sbet[e * 64 + tid] : gbet[(e - 2) * 64 + tid];
        }
    }
    if (tid < 64) ((float*)(smem + PGW))[tid] = (gslot == 0) ? sgw2[tid] : ggw2[(gslot - 1) * 64 + tid];
    if (tid < 2)  ((float*)(smem + PGB))[tid] = (gslot == 0) ? sgb2[tid] : ggb2[(gslot - 1) * 2 + tid];
    __syncthreads();

    if (tid < 128) {
        const __half2* gp = (const __half2*)(g_Hh + (size_t)(t0 + tid) * NCATP + 384 + gslot * 32);
        const float* gw = (const float*)(smem + PGW);
        float l0 = ((const float*)(smem + PGB))[0];
        float l1 = ((const float*)(smem + PGB))[1];
#pragma unroll
        for (int i = 0; i < 16; i++) {
            float2 h = __half22float2(gp[i]);
            l0 += h.x * gw[(2 * i) * 2]     + h.y * gw[(2 * i + 1) * 2];
            l1 += h.x * gw[(2 * i) * 2 + 1] + h.y * gw[(2 * i + 1) * 2 + 1];
        }
        float mx = fmaxf(l0, l1);
        float ea = __expf(l0 - mx), eb = __expf(l1 - mx);
        float inv = 1.f / (ea + eb);
        ((float2*)(smem + WG7))[tid] = make_float2(ea * inv, eb * inv);
    }

    const int mi = lane >> 3;
    const int a_row = (lane & 7) + ((mi & 1) << 3);
    const int akb = (mi >= 2) ? 1 : 0;
    const int tokb = wr * 32;

    float c2[2][4][4];
#pragma unroll
    for (int i = 0; i < 2; i++)
#pragma unroll
        for (int j = 0; j < 4; j++)
#pragma unroll
            for (int u = 0; u < 4; u++) c2[i][j][u] = 0.f;
    {
        const uint32_t aA = sb + A7 + (uint32_t)((tokb + a_row) * 256);
        const uint32_t bA = sb + W27 + (uint32_t)(ws * 5120 + (lane & 15) * 80);
#pragma unroll
        for (int kt = 0; kt < 4; kt++) {
            uint32_t aseg = (uint32_t)(((ws * 8 + kt * 2 + akb) ^ (lane & 7)) << 4);
            uint32_t a0[4], a1[4];
            ldsm_x4(a0, aA + aseg);
            ldsm_x4(a1, aA + 4096 + aseg);
#pragma unroll
            for (int nt = 0; nt < 4; nt++) {
                uint32_t b[2];
                ldsm_x2t(b, bA + (uint32_t)(kt * 16 * 80 + nt * 16));
                mma_f16(c2[0][nt], a0, b[0], b[1]);
                mma_f16(c2[1][nt], a1, b[0], b[1]);
            }
        }
    }
    {
        const float* b2v = (const float*)(smem + PB2) + ws * 32;
        char* h2b = smem + H27 + ws * 10240;
#pragma unroll
        for (int mt = 0; mt < 2; mt++)
#pragma unroll
            for (int nt = 0; nt < 4; nt++) {
                int c0 = nt * 8 + 2 * (lane & 3);
                int r  = tokb + mt * 16 + (lane >> 2);
                float b0 = b2v[c0], b1 = b2v[c0 + 1];
                float y0 = silu_f(c2[mt][nt][0] + b0);
                float y1 = silu_f(c2[mt][nt][1] + b1);
                float y2 = silu_f(c2[mt][nt][2] + b0);
                float y3 = silu_f(c2[mt][nt][3] + b1);
                *(__half2*)(h2b + r * 80 + c0 * 2)       = __floats2half2_rn(y0, y1);
                *(__half2*)(h2b + (r + 8) * 80 + c0 * 2) = __floats2half2_rn(y2, y3);
            }
    }
    __syncthreads();

    float c3[2][8][4];
#pragma unroll
    for (int i = 0; i < 2; i++)
#pragma unroll
        for (int j = 0; j < 8; j++)
#pragma unroll
            for (int u = 0; u < 4; u++) c3[i][j][u] = 0.f;
    {
        const uint32_t aA = sb + H27 + (uint32_t)(ws * 10240 + (tokb + a_row) * 80);
        const uint32_t bA = sb + W37 + (uint32_t)(ws * 4608 + (lane & 15) * 144);
#pragma unroll
        for (int kt = 0; kt < 2; kt++) {
            uint32_t aoff = (uint32_t)(kt * 32 + akb * 16);
            uint32_t a0[4], a1[4];
            ldsm_x4(a0, aA + aoff);
            ldsm_x4(a1, aA + 16 * 80 + aoff);
#pragma unroll
            for (int nt = 0; nt < 8; nt++) {
                uint32_t b[2];
                ldsm_x2t(b, bA + (uint32_t)(kt * 16 * 144 + nt * 16));
                mma_f16(c3[0][nt], a0, b[0], b[1]);
                mma_f16(c3[1][nt], a1, b[0], b[1]);
            }
        }
    }

    const float* b3v = (const float*)(smem + PB3) + ws * 64;
    const float* gmv = (const float*)(smem + PGM) + ws * 64;
    const float* btv = (const float*)(smem + PBT) + ws * 64;
    const unsigned FULL = 0xffffffffu;

    auto ln_acc = [&](bool add) {
#pragma unroll
        for (int mt = 0; mt < 2; mt++)
#pragma unroll
            for (int rh = 0; rh < 2; rh++) {
                float s1 = 0.f;
#pragma unroll
                for (int nt = 0; nt < 8; nt++) {
                    int c0 = nt * 8 + 2 * (lane & 3);
                    float v0 = c3[mt][nt][rh * 2]     + b3v[c0];
                    float v1 = c3[mt][nt][rh * 2 + 1] + b3v[c0 + 1];
                    s1 += v0 + v1;
                }
                s1 += __shfl_xor_sync(FULL, s1, 1);
                s1 += __shfl_xor_sync(FULL, s1, 2);
                float mu = s1 * (1.f / 64.f);
                float s2 = 0.f;
#pragma unroll
                for (int nt = 0; nt < 8; nt++) {
                    int c0 = nt * 8 + 2 * (lane & 3);
                    float d0 = c3[mt][nt][rh * 2]     + b3v[c0]     - mu;
                    float d1 = c3[mt][nt][rh * 2 + 1] + b3v[c0 + 1] - mu;
                    s2 += d0 * d0 + d1 * d1;
                }
                s2 += __shfl_xor_sync(FULL, s2, 1);
                s2 += __shfl_xor_sync(FULL, s2, 2);
                float x = s2 * (1.f / 64.f) + LN_EPS;
                float rinv = rsqrtf(x);
                rinv = rinv * (1.5f - 0.5f * x * rinv * rinv);

                int row = tokb + mt * 16 + (lane >> 2) + rh * 8;
                float wg = ((const float*)(smem + WG7))[row * 2 + ws];
                float* zr = (float*)(smem + ZAC7) + row * 68;
#pragma unroll
                for (int nt = 0; nt < 8; nt++) {
                    int c0 = nt * 8 + 2 * (lane & 3);
                    float d0 = c3[mt][nt][rh * 2]     + b3v[c0]     - mu;
                    float d1 = c3[mt][nt][rh * 2 + 1] + b3v[c0 + 1] - mu;
                    float z0 = wg * (gmv[c0] * d0 * rinv + btv[c0]);
                    float z1 = wg * (gmv[c0 + 1] * d1 * rinv + btv[c0 + 1]);
                    if (add) { zr[c0] += z0; zr[c0 + 1] += z1; }
                    else     { zr[c0]  = z0; zr[c0 + 1]  = z1; }
                }
            }
    };

    if (ws == 0) ln_acc(false);
    __syncthreads();
    if (ws == 1) ln_acc(true);
    __syncthreads();

    float* ob = out + ((size_t)p * B_TOK + t0) * D_OUT;
#pragma unroll
    for (int k = 0; k < 8; k++) {
        int lin = tid + k * 256;
        int row = lin >> 4, c4 = (lin & 15) * 4;
        float4 v = *(float4*)((float*)(smem + ZAC7) + row * 68 + c4);
        *(float4*)(ob + (size_t)row * D_OUT + c4) = v;
    }
}

// ---------------------------------------------------------------------------
// Launch
// ---------------------------------------------------------------------------
extern "C" void kernel_launch(void* const* d_in, const int* in_sizes, int n_in,
                              void* d_out, int out_size) {
    (void)in_sizes; (void)n_in; (void)out_size;
    const float* v    = (const float*)d_in[0];
    const float* sw1  = (const float*)d_in[1];
    const float* sb1  = (const float*)d_in[2];
    const float* sw2  = (const float*)d_in[3];
    const float* sb2  = (const float*)d_in[4];
    const float* sw3  = (const float*)d_in[5];
    const float* sb3  = (const float*)d_in[6];
    const float* sgam = (const float*)d_in[7];
    const float* sbet = (const float*)d_in[8];
    const float* sgw1 = (const float*)d_in[9];
    const float* sgb1 = (const float*)d_in[10];
    const float* sgw2 = (const float*)d_in[11];
    const float* sgb2 = (const float*)d_in[12];
    const float* gw1  = (const float*)d_in[13];
    const float* gb1  = (const float*)d_in[14];
    const float* gw2  = (const float*)d_in[15];
    const float* gb2  = (const float*)d_in[16];
    const float* gw3  = (const float*)d_in[17];
    const float* gb3  = (const float*)d_in[18];
    const float* ggam = (const float*)d_in[19];
    const float* gbet = (const float*)d_in[20];
    const float* ggw1 = (const float*)d_in[21];
    const float* ggb1 = (const float*)d_in[22];
    const float* ggw2 = (const float*)d_in[23];
    const float* ggb2 = (const float*)d_in[24];
    float* out = (float*)d_out;

    prep_kernel<<<256, 256>>>(sw1, sb1, gw1, gb1, sgw1, sgb1, ggw1, ggb1);

    cudaFuncSetAttribute(gemm1_mma_kernel, cudaFuncAttributeMaxDynamicSharedMemorySize, GEMM_SMEM);
    dim3 g1(NCATP / 128, B_TOK / 128);
    gemm1_mma_kernel<<<g1, 256, GEMM_SMEM>>>(v);

    cudaFuncSetAttribute(tail7_kernel, cudaFuncAttributeMaxDynamicSharedMemorySize, T7_SMEM);
    dim3 g2(B_TOK / 128, 3);
    tail7_kernel<<<g2, 256, T7_SMEM>>>(sw2, sb2, sw3, sb3, sgam, sbet, sgw2, sgb2,
                                       gw2, gb2, gw3, gb3, ggam, gbet, ggw2, ggb2, out);
}